// round 2
// baseline (speedup 1.0000x reference)
#include <cuda_runtime.h>
#include <cuda.h>
#include <cuda_bf16.h>
#include <cstdint>
#include <cstddef>

// Problem dims (fixed by the dataset)
#define BATCH 4
#define MDIM 2048
#define NDIM 2048
#define KDIM 2048

// GEMM tiling
#define TILE_M 128
#define TILE_N 128
#define KC 64                    // K per chunk: 64 bf16 = 128B row = SW128 atom
#define NCHUNK (KDIM / KC)       // 32
#define STAGES 3

// Per-stage SMEM layout (each tile 128 rows x 128 bytes, 1024-aligned)
#define OFF_AH 0
#define OFF_AL 16384
#define OFF_BH 32768
#define OFF_BL 49152
#define STAGE_BYTES 65536
#define SMEM_CTRL 1024
#define SMEM_TOTAL (SMEM_CTRL + STAGES * STAGE_BYTES)   // 197632

// ---------------------------------------------------------------------------
// Scratch: bf16 hi/lo splits of A [B,M,K]; B transposed to [B,N,K] hi/lo
// ---------------------------------------------------------------------------
__device__ alignas(1024) __nv_bfloat16 g_Ah[(size_t)BATCH * MDIM * KDIM];
__device__ alignas(1024) __nv_bfloat16 g_Al[(size_t)BATCH * MDIM * KDIM];
__device__ alignas(1024) __nv_bfloat16 g_Bh[(size_t)BATCH * NDIM * KDIM];
__device__ alignas(1024) __nv_bfloat16 g_Bl[(size_t)BATCH * NDIM * KDIM];

// ---------------------------------------------------------------------------
// PTX helpers — sm_90-class only (NO 'a'-suffix features; target is sm_103)
// ---------------------------------------------------------------------------
__device__ __forceinline__ uint32_t smem_u32(const void* p) {
    uint32_t a;
    asm("{ .reg .u64 t; cvta.to.shared.u64 t, %1; cvt.u32.u64 %0, t; }"
        : "=r"(a) : "l"(p));
    return a;
}

#define MBARRIER_INIT(addr, cnt) \
    asm volatile("mbarrier.init.shared.b64 [%0], %1;" :: "r"(addr), "r"(cnt) : "memory")

#define MBARRIER_EXPECT_TX(addr, bytes) \
    asm volatile("mbarrier.arrive.expect_tx.shared.b64 _, [%0], %1;" \
                 :: "r"(addr), "r"(bytes) : "memory")

#define MBAR_WAIT(addr, parity) do {                                          \
    asm volatile(                                                             \
        "{\n\t.reg .pred P1;\n\t"                                             \
        "WAIT_LOOP_%=:\n\t"                                                   \
        "mbarrier.try_wait.parity.acquire.cta.shared::cta.b64 P1, [%0], %1, 0x989680;\n\t" \
        "@P1 bra.uni WAIT_DONE_%=;\n\t"                                       \
        "bra.uni WAIT_LOOP_%=;\n\t"                                           \
        "WAIT_DONE_%=:\n\t}"                                                  \
        :: "r"((uint32_t)(addr)), "r"((uint32_t)(parity)) : "memory");        \
} while (0)

__device__ __forceinline__ void tma2d(uint32_t smem_dst, const CUtensorMap* map,
                                      int x, int y, uint32_t mbar) {
    asm volatile(
        "cp.async.bulk.tensor.2d.shared::cta.global.tile.mbarrier::complete_tx::bytes "
        "[%0], [%1, {%2, %3}], [%4];"
        :: "r"(smem_dst), "l"(map), "r"(x), "r"(y), "r"(mbar)
        : "memory");
}

__device__ __forceinline__ void ldsm_x4(uint32_t* r, uint32_t addr) {
    asm volatile("ldmatrix.sync.aligned.m8n8.x4.shared.b16 {%0,%1,%2,%3}, [%4];"
                 : "=r"(r[0]), "=r"(r[1]), "=r"(r[2]), "=r"(r[3]) : "r"(addr));
}

__device__ __forceinline__ void mma16816(float* d, const uint32_t* a,
                                         uint32_t b0, uint32_t b1) {
    asm volatile(
        "mma.sync.aligned.m16n8k16.row.col.f32.bf16.bf16.f32 "
        "{%0,%1,%2,%3}, {%4,%5,%6,%7}, {%8,%9}, {%0,%1,%2,%3};"
        : "+f"(d[0]), "+f"(d[1]), "+f"(d[2]), "+f"(d[3])
        : "r"(a[0]), "r"(a[1]), "r"(a[2]), "r"(a[3]), "r"(b0), "r"(b1));
}

// ---------------------------------------------------------------------------
// Conversion kernels
// ---------------------------------------------------------------------------
__global__ void cvtA_kernel(const float* __restrict__ a) {
    const size_t n4 = (size_t)BATCH * MDIM * KDIM / 4;
    const float4* a4 = (const float4*)a;
    uint2* hi = (uint2*)g_Ah;
    uint2* lo = (uint2*)g_Al;
    for (size_t i = (size_t)blockIdx.x * blockDim.x + threadIdx.x; i < n4;
         i += (size_t)gridDim.x * blockDim.x) {
        float4 v = a4[i];
        __nv_bfloat16 h0 = __float2bfloat16_rn(v.x);
        __nv_bfloat16 h1 = __float2bfloat16_rn(v.y);
        __nv_bfloat16 h2 = __float2bfloat16_rn(v.z);
        __nv_bfloat16 h3 = __float2bfloat16_rn(v.w);
        __nv_bfloat16 l0 = __float2bfloat16_rn(v.x - __bfloat162float(h0));
        __nv_bfloat16 l1 = __float2bfloat16_rn(v.y - __bfloat162float(h1));
        __nv_bfloat16 l2 = __float2bfloat16_rn(v.z - __bfloat162float(h2));
        __nv_bfloat16 l3 = __float2bfloat16_rn(v.w - __bfloat162float(h3));
        uint2 hv, lv;
        hv.x = (uint32_t)__bfloat16_as_ushort(h0) | ((uint32_t)__bfloat16_as_ushort(h1) << 16);
        hv.y = (uint32_t)__bfloat16_as_ushort(h2) | ((uint32_t)__bfloat16_as_ushort(h3) << 16);
        lv.x = (uint32_t)__bfloat16_as_ushort(l0) | ((uint32_t)__bfloat16_as_ushort(l1) << 16);
        lv.y = (uint32_t)__bfloat16_as_ushort(l2) | ((uint32_t)__bfloat16_as_ushort(l3) << 16);
        hi[i] = hv;
        lo[i] = lv;
    }
}

// B[b][k][n] (n contiguous) -> Bt[b][n][k] (k contiguous), split hi/lo
__global__ void cvtB_kernel(const float* __restrict__ bsrc) {
    __shared__ float t[32][33];
    const int b = blockIdx.z;
    const int n0 = blockIdx.x * 32;
    const int k0 = blockIdx.y * 32;
    const int tx = threadIdx.x, ty = threadIdx.y;
    const float* src = bsrc + (size_t)b * KDIM * NDIM;
#pragma unroll
    for (int j = 0; j < 32; j += 8)
        t[ty + j][tx] = src[(size_t)(k0 + ty + j) * NDIM + n0 + tx];
    __syncthreads();
    const size_t base = (size_t)b * NDIM * KDIM;
#pragma unroll
    for (int j = 0; j < 32; j += 8) {
        float v = t[tx][ty + j];
        __nv_bfloat16 h = __float2bfloat16_rn(v);
        __nv_bfloat16 l = __float2bfloat16_rn(v - __bfloat162float(h));
        size_t o = base + (size_t)(n0 + ty + j) * KDIM + (k0 + tx);
        g_Bh[o] = h;
        g_Bl[o] = l;
    }
}

// ---------------------------------------------------------------------------
// GEMM: 128x128 tile per CTA, bf16x3 split, TMA(SW128) + ldmatrix + mma.sync
// 256 threads = 8 warps, warp grid 4(M) x 2(N), warp tile 32x64.
// ---------------------------------------------------------------------------
__global__ void __launch_bounds__(256, 1) gemm_kernel(
    const __grid_constant__ CUtensorMap mAh,
    const __grid_constant__ CUtensorMap mAl,
    const __grid_constant__ CUtensorMap mBh,
    const __grid_constant__ CUtensorMap mBl,
    float* __restrict__ C)
{
    extern __shared__ char smem[];
    const uint32_t sb = smem_u32(smem);
    const int tid = threadIdx.x;
    const int wid = tid >> 5;
    const int lane = tid & 31;
    const int warpM = wid & 3;        // 4 groups of 32 rows
    const int warpN = wid >> 2;       // 2 groups of 64 cols

    const int tn = blockIdx.x;
    const int tm = blockIdx.y;
    const int bb = blockIdx.z;

    if (tid == 0) {
#pragma unroll
        for (int s = 0; s < STAGES; s++) MBARRIER_INIT(sb + 8 * s, 1);
        asm volatile("fence.proxy.async.shared::cta;" ::: "memory");
    }
    __syncthreads();

    const int rowA = bb * MDIM + tm * TILE_M;
    const int rowB = bb * NDIM + tn * TILE_N;

    // Prologue: fill all stages
    if (tid == 0) {
#pragma unroll
        for (int s = 0; s < STAGES; s++) {
            uint32_t st = sb + SMEM_CTRL + s * STAGE_BYTES;
            MBARRIER_EXPECT_TX(sb + 8 * s, (uint32_t)STAGE_BYTES);
            tma2d(st + OFF_AH, &mAh, s * KC, rowA, sb + 8 * s);
            tma2d(st + OFF_AL, &mAl, s * KC, rowA, sb + 8 * s);
            tma2d(st + OFF_BH, &mBh, s * KC, rowB, sb + 8 * s);
            tma2d(st + OFF_BL, &mBl, s * KC, rowB, sb + 8 * s);
        }
    }

    // ldmatrix addressing (SW128 swizzle = XOR bits[6:4] with row&7)
    const int r15 = lane & 15;
    const int kh = lane >> 4;                 // which 8-k half
    const uint32_t xorv = (uint32_t)((lane & 7) << 4);
    uint32_t kpart[4];
#pragma unroll
    for (int ks = 0; ks < 4; ks++)
        kpart[ks] = ((uint32_t)(ks * 32 + kh * 16)) ^ xorv;

    // Tile-local row byte bases
    uint32_t aRowOff[2], bRowOff[4];
#pragma unroll
    for (int mt = 0; mt < 2; mt++)
        aRowOff[mt] = (uint32_t)(warpM * 32 + mt * 16 + r15) * 128;
#pragma unroll
    for (int ng = 0; ng < 4; ng++)
        bRowOff[ng] = (uint32_t)(warpN * 64 + ng * 16 + r15) * 128;

    float acc[2][8][4];
#pragma unroll
    for (int mt = 0; mt < 2; mt++)
#pragma unroll
        for (int nt = 0; nt < 8; nt++)
#pragma unroll
            for (int i = 0; i < 4; i++) acc[mt][nt][i] = 0.0f;

    int pf[STAGES] = {0, 0, 0};

    for (int c = 0; c < NCHUNK; c++) {
        const int s = c % STAGES;
        MBAR_WAIT(sb + 8 * s, pf[s]);
        pf[s] ^= 1;
        const uint32_t st = sb + SMEM_CTRL + s * STAGE_BYTES;

#pragma unroll
        for (int ks = 0; ks < 4; ks++) {
            uint32_t ah[2][4], al[2][4], bh[4][4], bl[4][4];
#pragma unroll
            for (int mt = 0; mt < 2; mt++) {
                ldsm_x4(ah[mt], st + OFF_AH + aRowOff[mt] + kpart[ks]);
                ldsm_x4(al[mt], st + OFF_AL + aRowOff[mt] + kpart[ks]);
            }
#pragma unroll
            for (int ng = 0; ng < 4; ng++) {
                ldsm_x4(bh[ng], st + OFF_BH + bRowOff[ng] + kpart[ks]);
                ldsm_x4(bl[ng], st + OFF_BL + bRowOff[ng] + kpart[ks]);
            }
            // B frag for ntile nt: ng = nt>>1; even nt -> {r0,r2}, odd -> {r1,r3}
#pragma unroll
            for (int mt = 0; mt < 2; mt++) {
#pragma unroll
                for (int nt = 0; nt < 8; nt++) {
                    const int ng = nt >> 1;
                    const int o = nt & 1;
                    mma16816(acc[mt][nt], ah[mt], bh[ng][o], bh[ng][o + 2]);
                    mma16816(acc[mt][nt], al[mt], bh[ng][o], bh[ng][o + 2]);
                    mma16816(acc[mt][nt], ah[mt], bl[ng][o], bl[ng][o + 2]);
                }
            }
        }

        __syncthreads();   // all warps done reading stage s
        if (tid == 0 && c + STAGES < NCHUNK) {
            const int kk = (c + STAGES) * KC;
            MBARRIER_EXPECT_TX(sb + 8 * s, (uint32_t)STAGE_BYTES);
            tma2d(st + OFF_AH, &mAh, kk, rowA, sb + 8 * s);
            tma2d(st + OFF_AL, &mAl, kk, rowA, sb + 8 * s);
            tma2d(st + OFF_BH, &mBh, kk, rowB, sb + 8 * s);
            tma2d(st + OFF_BL, &mBl, kk, rowB, sb + 8 * s);
        }
    }

    // Epilogue: d frag: c0,c1 -> row lane/4, cols 2(lane%4)+{0,1}; c2,c3 -> row+8
    const int cRow0 = tm * TILE_M + warpM * 32 + (lane >> 2);
    const int cCol0 = tn * TILE_N + warpN * 64 + (lane & 3) * 2;
    float* Cb = C + (size_t)bb * MDIM * NDIM;
#pragma unroll
    for (int mt = 0; mt < 2; mt++) {
        const int r0 = cRow0 + mt * 16;
        float* rp0 = Cb + (size_t)r0 * NDIM + cCol0;
        float* rp1 = Cb + (size_t)(r0 + 8) * NDIM + cCol0;
#pragma unroll
        for (int nt = 0; nt < 8; nt++) {
            *reinterpret_cast<float2*>(rp0 + nt * 8) =
                make_float2(acc[mt][nt][0], acc[mt][nt][1]);
            *reinterpret_cast<float2*>(rp1 + nt * 8) =
                make_float2(acc[mt][nt][2], acc[mt][nt][3]);
        }
    }
}

// ---------------------------------------------------------------------------
// Host launch
// ---------------------------------------------------------------------------
typedef CUresult (*PFN_tmap_encode)(
    CUtensorMap*, CUtensorMapDataType, cuuint32_t, void*,
    const cuuint64_t*, const cuuint64_t*, const cuuint32_t*, const cuuint32_t*,
    CUtensorMapInterleave, CUtensorMapSwizzle, CUtensorMapL2promotion,
    CUtensorMapFloatOOBfill);

static void make_map_bf16(PFN_tmap_encode enc, CUtensorMap* m, void* base,
                          cuuint64_t dim0, cuuint64_t dim1,
                          cuuint32_t box0, cuuint32_t box1) {
    cuuint64_t gd[2] = {dim0, dim1};
    cuuint64_t gs[1] = {dim0 * sizeof(__nv_bfloat16)};
    cuuint32_t bd[2] = {box0, box1};
    cuuint32_t es[2] = {1, 1};
    enc(m, CU_TENSOR_MAP_DATA_TYPE_BFLOAT16, 2, base, gd, gs, bd, es,
        CU_TENSOR_MAP_INTERLEAVE_NONE, CU_TENSOR_MAP_SWIZZLE_128B,
        CU_TENSOR_MAP_L2_PROMOTION_L2_128B, CU_TENSOR_MAP_FLOAT_OOB_FILL_NONE);
}

extern "C" void kernel_launch(void* const* d_in, const int* in_sizes, int n_in,
                              void* d_out, int out_size) {
    (void)in_sizes; (void)n_in; (void)out_size;
    const float* A = (const float*)d_in[0];
    const float* B = (const float*)d_in[1];
    float* C = (float*)d_out;

    cvtA_kernel<<<2048, 256>>>(A);
    cvtB_kernel<<<dim3(NDIM / 32, KDIM / 32, BATCH), dim3(32, 8)>>>(B);

    void *pAh = nullptr, *pAl = nullptr, *pBh = nullptr, *pBl = nullptr;
    cudaGetSymbolAddress(&pAh, g_Ah);
    cudaGetSymbolAddress(&pAl, g_Al);
    cudaGetSymbolAddress(&pBh, g_Bh);
    cudaGetSymbolAddress(&pBl, g_Bl);

    void* fn = nullptr;
    cudaDriverEntryPointQueryResult qr;
    cudaGetDriverEntryPoint("cuTensorMapEncodeTiled", &fn, cudaEnableDefault, &qr);
    if (!fn) return;
    PFN_tmap_encode enc = (PFN_tmap_encode)fn;

    CUtensorMap mAh, mAl, mBh, mBl;
    make_map_bf16(enc, &mAh, pAh, KDIM, (cuuint64_t)BATCH * MDIM, KC, TILE_M);
    make_map_bf16(enc, &mAl, pAl, KDIM, (cuuint64_t)BATCH * MDIM, KC, TILE_M);
    make_map_bf16(enc, &mBh, pBh, KDIM, (cuuint64_t)BATCH * NDIM, KC, TILE_N);
    make_map_bf16(enc, &mBl, pBl, KDIM, (cuuint64_t)BATCH * NDIM, KC, TILE_N);

    cudaFuncSetAttribute(gemm_kernel, cudaFuncAttributeMaxDynamicSharedMemorySize,
                         SMEM_TOTAL);
    gemm_kernel<<<dim3(NDIM / TILE_N, MDIM / TILE_M, BATCH), 256, SMEM_TOTAL>>>(
        mAh, mAl, mBh, mBl, C);
}